// round 5
// baseline (speedup 1.0000x reference)
#include <cuda_runtime.h>
#include <float.h>

#define N_NODES 50000
#define E_EDGES 800000
#define HDIM    256

// ---------------- scratch (static device globals; no runtime allocation) ----
__device__ int   g_mode;              // 0 = edge_index is int32, 1 = int64
__device__ int   g_deg[N_NODES];
__device__ int   g_cursor[N_NODES];
__device__ int   g_rowptr[N_NODES + 1];
__device__ int   g_srcs[E_EDGES];
__device__ float g_agg [N_NODES * HDIM];
__device__ float g_buf1[N_NODES * HDIM];
__device__ float g_buf2[N_NODES * HDIM];

// ---------------- edge dtype probe -----------------------------------------
// If the data is really int64, every 8-byte read of a node index is in [0, N).
// If it is int32 (JAX default x64-disabled downcast), an 8-byte read packs two
// random indices -> value >= 2^32 unless the high word is 0 (prob ~1/50000 per
// sample; 64 samples make misdetection essentially impossible).
__global__ void detect_kernel(const void* __restrict__ ei) {
    const long long* p = (const long long*)ei;
    int mode = 1;
    for (int i = 0; i < 64; ++i) {
        long long v = p[i];
        if (v < 0 || v >= N_NODES) { mode = 0; break; }
    }
    g_mode = mode;
}

__device__ __forceinline__ int edge_at(const void* ei, long long idx) {
    if (g_mode) return (int)((const long long*)ei)[idx];
    return ((const int*)ei)[idx];
}

// ---------------- CSR build ------------------------------------------------
__global__ void zero2_kernel(int n) {
    int i = blockIdx.x * blockDim.x + threadIdx.x;
    if (i < n) { g_deg[i] = 0; g_cursor[i] = 0; }
}

__global__ void count_kernel(const void* __restrict__ ei, int E) {
    int e = blockIdx.x * blockDim.x + threadIdx.x;
    if (e < E) {
        int dst = edge_at(ei, (long long)E + e);
        atomicAdd(&g_deg[dst], 1);
    }
}

// single-block chunked exclusive scan over g_deg -> g_rowptr
__global__ void scan_kernel(int n) {
    __shared__ int s[1024];
    int tid = threadIdx.x;
    int chunk = (n + 1023) / 1024;
    int start = tid * chunk;
    int sum = 0;
    for (int i = 0; i < chunk; ++i) {
        int idx = start + i;
        if (idx < n) sum += g_deg[idx];
    }
    s[tid] = sum;
    __syncthreads();
    for (int off = 1; off < 1024; off <<= 1) {
        int v = 0;
        if (tid >= off) v = s[tid - off];
        __syncthreads();
        s[tid] += v;
        __syncthreads();
    }
    int pre = (tid == 0) ? 0 : s[tid - 1];
    for (int i = 0; i < chunk; ++i) {
        int idx = start + i;
        if (idx < n) { g_rowptr[idx] = pre; pre += g_deg[idx]; }
    }
    if (tid == 1023) g_rowptr[n] = s[1023];
}

__global__ void scatter_kernel(const void* __restrict__ ei, int E) {
    int e = blockIdx.x * blockDim.x + threadIdx.x;
    if (e < E) {
        int dst = edge_at(ei, (long long)E + e);
        int src = edge_at(ei, e);
        int pos = g_rowptr[dst] + atomicAdd(&g_cursor[dst], 1);
        g_srcs[pos] = src;
    }
}

// ---------------- segment max (one block per node, thread = feature) -------
template <int F>
__global__ void segmax_kernel(const float* __restrict__ in, float* __restrict__ out) {
    int n = blockIdx.x;
    int f = threadIdx.x;
    int beg = g_rowptr[n], end = g_rowptr[n + 1];
    float m = -FLT_MAX;
    int e = beg;
    for (; e + 4 <= end; e += 4) {
        int s0 = g_srcs[e], s1 = g_srcs[e + 1], s2 = g_srcs[e + 2], s3 = g_srcs[e + 3];
        float v0 = in[s0 * F + f];
        float v1 = in[s1 * F + f];
        float v2 = in[s2 * F + f];
        float v3 = in[s3 * F + f];
        m = fmaxf(m, fmaxf(fmaxf(v0, v1), fmaxf(v2, v3)));
    }
    for (; e < end; ++e) m = fmaxf(m, in[g_srcs[e] * F + f]);
    out[n * F + f] = (beg == end) ? 0.0f : m;  // isolated nodes -> 0 (matches reference)
}

// ---------------- fused dual-GEMM + bias + relu ----------------------------
// C[M,256] = relu(A0[M,K]@W0[K,256] + A1[M,K]@W1[K,256] + bias)
// Tile: BM=128, BN=64, BK=16. 256 threads, 8x4 microtile per thread.
#define TBM 128
#define TBN 64
#define TBK 16

__global__ __launch_bounds__(256) void gemm2_bias_relu(
    const float* __restrict__ A0, const float* __restrict__ W0,
    const float* __restrict__ A1, const float* __restrict__ W1,
    const float* __restrict__ bias, float* __restrict__ C,
    int M, int K)
{
    const int H = HDIM;
    __shared__ float As[TBK][TBM];
    __shared__ float Bs[TBK][TBN];

    int tid = threadIdx.x;
    int m0 = blockIdx.x * TBM;
    int h0 = blockIdx.y * TBN;
    int tx = tid & 15;   // col group: cols h0 + tx*4 .. +3
    int ty = tid >> 4;   // row group: rows m0 + ty*8 .. +7

    float acc[8][4];
#pragma unroll
    for (int i = 0; i < 8; ++i)
#pragma unroll
        for (int j = 0; j < 4; ++j) acc[i][j] = 0.0f;

    int arow = tid >> 2;        // 0..63 (two rows per thread: +0, +64)
    int ak   = (tid & 3) * 4;   // k offset within tile
    int brow = tid >> 4;        // 0..15
    int bh   = (tid & 15) * 4;  // h offset within tile

#pragma unroll 1
    for (int phase = 0; phase < 2; ++phase) {
        const float* __restrict__ A = phase ? A1 : A0;
        const float* __restrict__ W = phase ? W1 : W0;
#pragma unroll 1
        for (int k0 = 0; k0 < K; k0 += TBK) {
            // load A tile (128x16), transposed into As[k][m]
#pragma unroll
            for (int l = 0; l < 2; ++l) {
                int r = arow + l * 64;
                int gm = m0 + r;
                float4 v = make_float4(0.f, 0.f, 0.f, 0.f);
                if (gm < M) v = *(const float4*)&A[(long long)gm * K + k0 + ak];
                As[ak + 0][r] = v.x;
                As[ak + 1][r] = v.y;
                As[ak + 2][r] = v.z;
                As[ak + 3][r] = v.w;
            }
            // load B tile (16x64)
            {
                float4 v = *(const float4*)&W[(k0 + brow) * H + h0 + bh];
                *(float4*)&Bs[brow][bh] = v;
            }
            __syncthreads();
#pragma unroll
            for (int kk = 0; kk < TBK; ++kk) {
                float a[8], b[4];
                float4 a0 = *(const float4*)&As[kk][ty * 8];
                float4 a1 = *(const float4*)&As[kk][ty * 8 + 4];
                a[0] = a0.x; a[1] = a0.y; a[2] = a0.z; a[3] = a0.w;
                a[4] = a1.x; a[5] = a1.y; a[6] = a1.z; a[7] = a1.w;
                float4 bb = *(const float4*)&Bs[kk][tx * 4];
                b[0] = bb.x; b[1] = bb.y; b[2] = bb.z; b[3] = bb.w;
#pragma unroll
                for (int i = 0; i < 8; ++i)
#pragma unroll
                    for (int j = 0; j < 4; ++j) acc[i][j] += a[i] * b[j];
            }
            __syncthreads();
        }
    }

    float bj[4];
#pragma unroll
    for (int j = 0; j < 4; ++j) bj[j] = bias[h0 + tx * 4 + j];
#pragma unroll
    for (int i = 0; i < 8; ++i) {
        int gm = m0 + ty * 8 + i;
        if (gm < M) {
#pragma unroll
            for (int j = 0; j < 4; ++j) {
                float v = acc[i][j] + bj[j];
                C[(long long)gm * H + h0 + tx * 4 + j] = fmaxf(v, 0.0f);
            }
        }
    }
}

// ---------------- head: out[n] = dot(h[n,:256], w) + b ---------------------
__global__ void head_dot(const float* __restrict__ h, const float* __restrict__ w,
                         const float* __restrict__ b, float* __restrict__ out, int M) {
    int warp = (blockIdx.x * blockDim.x + threadIdx.x) >> 5;
    int lane = threadIdx.x & 31;
    if (warp >= M) return;
    const float* row = h + (long long)warp * HDIM;
    float s = 0.0f;
#pragma unroll
    for (int i = 0; i < HDIM; i += 32) s += row[i + lane] * w[i + lane];
#pragma unroll
    for (int o = 16; o; o >>= 1) s += __shfl_xor_sync(0xFFFFFFFFu, s, o);
    if (lane == 0) out[warp] = s + b[0];
}

// ---------------- launch ---------------------------------------------------
extern "C" void kernel_launch(void* const* d_in, const int* in_sizes, int n_in,
                              void* d_out, int out_size) {
    const float* x  = (const float*)d_in[0];
    const void*  ei = d_in[1];   // int32 or int64 — probed on device
    const float *Wl1 = (const float*)d_in[2],  *bl1 = (const float*)d_in[3],  *Wr1 = (const float*)d_in[4];
    const float *Wl2 = (const float*)d_in[5],  *bl2 = (const float*)d_in[6],  *Wr2 = (const float*)d_in[7];
    const float *Wla = (const float*)d_in[8],  *bla = (const float*)d_in[9],  *Wra = (const float*)d_in[10];
    const float *Wa  = (const float*)d_in[11], *ba  = (const float*)d_in[12];
    const float *Wlm = (const float*)d_in[13], *blm = (const float*)d_in[14], *Wrm = (const float*)d_in[15];
    const float *Wm  = (const float*)d_in[16], *bm  = (const float*)d_in[17];
    float* out = (float*)d_out;

    const int N = N_NODES;
    const int E = in_sizes[1] / 2;

    float *agg, *b1, *b2;
    cudaGetSymbolAddress((void**)&agg, g_agg);
    cudaGetSymbolAddress((void**)&b1,  g_buf1);
    cudaGetSymbolAddress((void**)&b2,  g_buf2);

    // dtype probe + CSR build (max aggregation is order-invariant -> deterministic)
    detect_kernel <<<1, 1>>>(ei);
    zero2_kernel  <<<(N + 255) / 256, 256>>>(N);
    count_kernel  <<<(E + 255) / 256, 256>>>(ei, E);
    scan_kernel   <<<1, 1024>>>(N);
    scatter_kernel<<<(E + 255) / 256, 256>>>(ei, E);

    dim3 gg((N + TBM - 1) / TBM, HDIM / TBN);

    // layer 1: h1 = relu(agg(x)@Wl1 + x@Wr1 + bl1)
    segmax_kernel<128><<<N, 128>>>(x, agg);
    gemm2_bias_relu<<<gg, 256>>>(agg, Wl1, x, Wr1, bl1, b1, N, 128);

    // layer 2: h2 = relu(agg(h1)@Wl2 + h1@Wr2 + bl2)
    segmax_kernel<256><<<N, 256>>>(b1, agg);
    gemm2_bias_relu<<<gg, 256>>>(agg, Wl2, b1, Wr2, bl2, b2, N, 256);

    // shared aggregation for both heads: agg(h2)
    segmax_kernel<256><<<N, 256>>>(b2, agg);

    // rtang head
    gemm2_bias_relu<<<gg, 256>>>(agg, Wla, b2, Wra, bla, b1, N, 256);
    head_dot<<<(N * 32 + 255) / 256, 256>>>(b1, Wa, ba, out, N);

    // movedis head
    gemm2_bias_relu<<<gg, 256>>>(agg, Wlm, b2, Wrm, blm, b1, N, 256);
    head_dot<<<(N * 32 + 255) / 256, 256>>>(b1, Wm, bm, out + N, N);
}

// round 7
// speedup vs baseline: 2.0336x; 2.0336x over previous
#include <cuda_runtime.h>
#include <float.h>
#include <stdint.h>

#define N_NODES 50000
#define E_EDGES 800000
#define HDIM    256

// ---------------- scratch (static device globals; no runtime allocation) ----
__device__ int   g_mode;              // 0 = edge_index is int32, 1 = int64
__device__ int   g_deg[N_NODES];
__device__ int   g_cursor[N_NODES];
__device__ int   g_rowptr[N_NODES + 1];
__device__ int   g_part[64];
__device__ int   g_srcs[E_EDGES];
__device__ float g_agg [N_NODES * HDIM];
__device__ float g_buf1[N_NODES * HDIM];
__device__ float g_buf2[N_NODES * HDIM];

// ---------------- edge dtype probe -----------------------------------------
__global__ void detect_kernel(const void* __restrict__ ei) {
    const long long* p = (const long long*)ei;
    int mode = 1;
    for (int i = 0; i < 64; ++i) {
        long long v = p[i];
        if (v < 0 || v >= N_NODES) { mode = 0; break; }
    }
    g_mode = mode;
}

__device__ __forceinline__ int edge_at(const void* ei, long long idx) {
    if (g_mode) return (int)((const long long*)ei)[idx];
    return ((const int*)ei)[idx];
}

// ---------------- CSR build ------------------------------------------------
__global__ void zero2_kernel(int n) {
    int i = blockIdx.x * blockDim.x + threadIdx.x;
    if (i < n) { g_deg[i] = 0; g_cursor[i] = 0; }
}

__global__ void count_kernel(const void* __restrict__ ei, int E) {
    int e = blockIdx.x * blockDim.x + threadIdx.x;
    if (e < E) atomicAdd(&g_deg[edge_at(ei, (long long)E + e)], 1);
}

// 3-phase parallel exclusive scan over g_deg -> g_rowptr
__global__ void part_sum_kernel(int n) {
    __shared__ int s[256];
    int b = blockIdx.x, tid = threadIdx.x;
    int base = b * 1024;
    int v = 0;
    for (int i = tid; i < 1024; i += 256) {
        int idx = base + i;
        if (idx < n) v += g_deg[idx];
    }
    s[tid] = v; __syncthreads();
    for (int o = 128; o; o >>= 1) { if (tid < o) s[tid] += s[tid + o]; __syncthreads(); }
    if (tid == 0) g_part[b] = s[0];
}

__global__ void part_scan_kernel(int nb) {
    if (threadIdx.x == 0) {
        int acc = 0;
        for (int b = 0; b < nb; ++b) { int t = g_part[b]; g_part[b] = acc; acc += t; }
    }
}

__global__ void local_scan_kernel(int n) {
    __shared__ int s[1024];
    int tid = threadIdx.x;
    int i = blockIdx.x * 1024 + tid;
    int v = (i < n) ? g_deg[i] : 0;
    s[tid] = v; __syncthreads();
    for (int off = 1; off < 1024; off <<= 1) {
        int t = (tid >= off) ? s[tid - off] : 0;
        __syncthreads();
        s[tid] += t;
        __syncthreads();
    }
    int off0 = g_part[blockIdx.x];
    if (i < n)      g_rowptr[i] = off0 + s[tid] - v;   // exclusive
    if (i == n - 1) g_rowptr[n] = off0 + s[tid];       // total
}

__global__ void scatter_kernel(const void* __restrict__ ei, int E) {
    int e = blockIdx.x * blockDim.x + threadIdx.x;
    if (e < E) {
        int dst = edge_at(ei, (long long)E + e);
        int src = edge_at(ei, e);
        int pos = g_rowptr[dst] + atomicAdd(&g_cursor[dst], 1);
        g_srcs[pos] = src;
    }
}

// ---------------- segment max (one block per node, thread = feature) -------
template <int F>
__global__ void segmax_kernel(const float* __restrict__ in, float* __restrict__ out) {
    int n = blockIdx.x;
    int f = threadIdx.x;
    int beg = g_rowptr[n], end = g_rowptr[n + 1];
    float m = -FLT_MAX;
    int e = beg;
    for (; e + 4 <= end; e += 4) {
        int s0 = g_srcs[e], s1 = g_srcs[e + 1], s2 = g_srcs[e + 2], s3 = g_srcs[e + 3];
        float v0 = in[s0 * F + f];
        float v1 = in[s1 * F + f];
        float v2 = in[s2 * F + f];
        float v3 = in[s3 * F + f];
        m = fmaxf(m, fmaxf(fmaxf(v0, v1), fmaxf(v2, v3)));
    }
    for (; e < end; ++e) m = fmaxf(m, in[g_srcs[e] * F + f]);
    out[n * F + f] = (beg == end) ? 0.0f : m;
}

// ---------------- TF32 tensor-core dual-GEMM + bias + relu -----------------
// C[M,256] = relu(A0[M,K]@W0[K,256] + A1[M,K]@W1[K,256] + bias)
// BM=128, BN=128, BK=32. 256 threads = 8 warps, warp tile 32m x 64n,
// mma.sync.m16n8k8 tf32 (2 m-frags x 8 n-frags per warp per k8-step).
#define GBM 128
#define GBN 128
#define GBK 32
#define AS_STRIDE 36    // [m][k] pad: frag-read banks 4r+c -> conflict-free
#define BS_STRIDE 136   // [k][n] pad: frag-read banks 8c+r -> conflict-free

__device__ __forceinline__ uint32_t f2tf32(float x) {
    uint32_t u; asm("cvt.rna.tf32.f32 %0, %1;" : "=r"(u) : "f"(x)); return u;
}

__device__ __forceinline__ void mma_tf32(float* c, const uint32_t* a, const uint32_t* b) {
    asm volatile(
        "mma.sync.aligned.m16n8k8.row.col.f32.tf32.tf32.f32 "
        "{%0,%1,%2,%3}, {%4,%5,%6,%7}, {%8,%9}, {%0,%1,%2,%3};\n"
        : "+f"(c[0]), "+f"(c[1]), "+f"(c[2]), "+f"(c[3])
        : "r"(a[0]), "r"(a[1]), "r"(a[2]), "r"(a[3]), "r"(b[0]), "r"(b[1]));
}

__global__ __launch_bounds__(256) void gemm2_tf32(
    const float* __restrict__ A0, const float* __restrict__ W0,
    const float* __restrict__ A1, const float* __restrict__ W1,
    const float* __restrict__ bias, float* __restrict__ C,
    int M, int K)
{
    __shared__ uint32_t As[GBM * AS_STRIDE];
    __shared__ uint32_t Bs[GBK * BS_STRIDE];
    const int tid  = threadIdx.x;
    const int lane = tid & 31, warp = tid >> 5;
    const int m0 = blockIdx.x * GBM, h0 = blockIdx.y * GBN;
    const int wm = warp >> 1, wn = warp & 1;   // 4x2 warp grid

    float acc[2][8][4];
#pragma unroll
    for (int i = 0; i < 2; ++i)
#pragma unroll
        for (int j = 0; j < 8; ++j)
#pragma unroll
            for (int q = 0; q < 4; ++q) acc[i][j][q] = 0.f;

    const int a_kw = 4 * (lane & 7);   // A writer k offset (quarter-warp = one row)
    const int r = lane >> 2, c = lane & 3;

    for (int phase = 0; phase < 2; ++phase) {
        const float* __restrict__ A = phase ? A1 : A0;
        const float* __restrict__ W = phase ? W1 : W0;
        for (int k0 = 0; k0 < K; k0 += GBK) {
            // stage A tile 128x32 (quarter-warp per row -> coalesced LDG, contig STS)
#pragma unroll
            for (int it = 0; it < 4; ++it) {
                int mr = warp * 16 + it * 4 + (lane >> 3);
                int gm = m0 + mr;
                float4 v = make_float4(0.f, 0.f, 0.f, 0.f);
                if (gm < M) v = *(const float4*)&A[(size_t)gm * K + k0 + a_kw];
                uint32_t* p = &As[mr * AS_STRIDE + a_kw];
                p[0] = f2tf32(v.x); p[1] = f2tf32(v.y);
                p[2] = f2tf32(v.z); p[3] = f2tf32(v.w);
            }
            // stage B tile 32x128 (warp per row -> 512B coalesced LDG, contig STS)
#pragma unroll
            for (int it = 0; it < 4; ++it) {
                int kr = warp * 4 + it;
                float4 v = *(const float4*)&W[(size_t)(k0 + kr) * HDIM + h0 + 4 * lane];
                uint32_t* p = &Bs[kr * BS_STRIDE + 4 * lane];
                p[0] = f2tf32(v.x); p[1] = f2tf32(v.y);
                p[2] = f2tf32(v.z); p[3] = f2tf32(v.w);
            }
            __syncthreads();
#pragma unroll
            for (int kt = 0; kt < 4; ++kt) {
                uint32_t af[2][4], bf[8][2];
#pragma unroll
                for (int i = 0; i < 2; ++i) {
                    int mb = wm * 32 + i * 16;
                    af[i][0] = As[(mb + r    ) * AS_STRIDE + kt * 8 + c    ];
                    af[i][1] = As[(mb + r + 8) * AS_STRIDE + kt * 8 + c    ];
                    af[i][2] = As[(mb + r    ) * AS_STRIDE + kt * 8 + c + 4];
                    af[i][3] = As[(mb + r + 8) * AS_STRIDE + kt * 8 + c + 4];
                }
#pragma unroll
                for (int j = 0; j < 8; ++j) {
                    int nb = wn * 64 + j * 8 + r;
                    bf[j][0] = Bs[(kt * 8 + c    ) * BS_STRIDE + nb];
                    bf[j][1] = Bs[(kt * 8 + c + 4) * BS_STRIDE + nb];
                }
#pragma unroll
                for (int i = 0; i < 2; ++i)
#pragma unroll
                    for (int j = 0; j < 8; ++j)
                        mma_tf32(acc[i][j], af[i], bf[j]);
            }
            __syncthreads();
        }
    }

    // epilogue: bias + relu
    int c2 = (lane & 3) * 2;
#pragma unroll
    for (int i = 0; i < 2; ++i) {
        int gmb = m0 + wm * 32 + i * 16;
#pragma unroll
        for (int j = 0; j < 8; ++j) {
            int h = h0 + wn * 64 + j * 8 + c2;
            float bv0 = bias[h], bv1 = bias[h + 1];
            int gma = gmb + r, gmc = gmb + r + 8;
            if (gma < M) {
                float2 o = make_float2(fmaxf(acc[i][j][0] + bv0, 0.f),
                                       fmaxf(acc[i][j][1] + bv1, 0.f));
                *(float2*)&C[(size_t)gma * HDIM + h] = o;
            }
            if (gmc < M) {
                float2 o = make_float2(fmaxf(acc[i][j][2] + bv0, 0.f),
                                       fmaxf(acc[i][j][3] + bv1, 0.f));
                *(float2*)&C[(size_t)gmc * HDIM + h] = o;
            }
        }
    }
}

// ---------------- head: out[n] = dot(h[n,:256], w) + b ---------------------
__global__ void head_dot(const float* __restrict__ h, const float* __restrict__ w,
                         const float* __restrict__ b, float* __restrict__ out, int M) {
    int warp = (blockIdx.x * blockDim.x + threadIdx.x) >> 5;
    int lane = threadIdx.x & 31;
    if (warp >= M) return;
    const float* row = h + (size_t)warp * HDIM;
    float s = 0.0f;
#pragma unroll
    for (int i = 0; i < HDIM; i += 32) s += row[i + lane] * w[i + lane];
#pragma unroll
    for (int o = 16; o; o >>= 1) s += __shfl_xor_sync(0xFFFFFFFFu, s, o);
    if (lane == 0) out[warp] = s + b[0];
}

// ---------------- launch ---------------------------------------------------
extern "C" void kernel_launch(void* const* d_in, const int* in_sizes, int n_in,
                              void* d_out, int out_size) {
    const float* x  = (const float*)d_in[0];
    const void*  ei = d_in[1];   // int32 or int64 — probed on device
    const float *Wl1 = (const float*)d_in[2],  *bl1 = (const float*)d_in[3],  *Wr1 = (const float*)d_in[4];
    const float *Wl2 = (const float*)d_in[5],  *bl2 = (const float*)d_in[6],  *Wr2 = (const float*)d_in[7];
    const float *Wla = (const float*)d_in[8],  *bla = (const float*)d_in[9],  *Wra = (const float*)d_in[10];
    const float *Wa  = (const float*)d_in[11], *ba  = (const float*)d_in[12];
    const float *Wlm = (const float*)d_in[13], *blm = (const float*)d_in[14], *Wrm = (const float*)d_in[15];
    const float *Wm  = (const float*)d_in[16], *bm  = (const float*)d_in[17];
    float* out = (float*)d_out;

    const int N = N_NODES;
    const int E = in_sizes[1] / 2;
    const int NB = (N + 1023) / 1024;

    float *agg, *b1, *b2;
    cudaGetSymbolAddress((void**)&agg, g_agg);
    cudaGetSymbolAddress((void**)&b1,  g_buf1);
    cudaGetSymbolAddress((void**)&b2,  g_buf2);

    // dtype probe + CSR build (max aggregation is order-invariant -> deterministic)
    detect_kernel    <<<1, 1>>>(ei);
    zero2_kernel     <<<(N + 255) / 256, 256>>>(N);
    count_kernel     <<<(E + 255) / 256, 256>>>(ei, E);
    part_sum_kernel  <<<NB, 256>>>(N);
    part_scan_kernel <<<1, 32>>>(NB);
    local_scan_kernel<<<NB, 1024>>>(N);
    scatter_kernel   <<<(E + 255) / 256, 256>>>(ei, E);

    dim3 gg((N + GBM - 1) / GBM, HDIM / GBN);

    // layer 1: h1 = relu(agg(x)@Wl1 + x@Wr1 + bl1)
    segmax_kernel<128><<<N, 128>>>(x, agg);
    gemm2_tf32<<<gg, 256>>>(agg, Wl1, x, Wr1, bl1, b1, N, 128);

    // layer 2: h2 = relu(agg(h1)@Wl2 + h1@Wr2 + bl2)
    segmax_kernel<256><<<N, 256>>>(b1, agg);
    gemm2_tf32<<<gg, 256>>>(agg, Wl2, b1, Wr2, bl2, b2, N, 256);

    // shared aggregation for both heads: agg(h2)
    segmax_kernel<256><<<N, 256>>>(b2, agg);

    // rtang head
    gemm2_tf32<<<gg, 256>>>(agg, Wla, b2, Wra, bla, b1, N, 256);
    head_dot<<<(N * 32 + 255) / 256, 256>>>(b1, Wa, ba, out, N);

    // movedis head
    gemm2_tf32<<<gg, 256>>>(agg, Wlm, b2, Wrm, blm, b1, N, 256);
    head_dot<<<(N * 32 + 255) / 256, 256>>>(b1, Wm, bm, out + N, N);
}

// round 8
// speedup vs baseline: 2.1405x; 1.0526x over previous
#include <cuda_runtime.h>
#include <float.h>
#include <stdint.h>

#define N_NODES 50000
#define E_EDGES 800000
#define HDIM    256

// ---------------- scratch (static device globals; no runtime allocation) ----
__device__ int   g_mode;              // 0 = edge_index is int32, 1 = int64
__device__ int   g_deg[N_NODES];
__device__ int   g_cursor[N_NODES];
__device__ int   g_rowptr[N_NODES + 1];
__device__ int   g_part[64];
__device__ int   g_srcs[E_EDGES];
__device__ float g_agg [N_NODES * HDIM];
__device__ float g_buf1[N_NODES * HDIM];
__device__ float g_buf2[N_NODES * HDIM];
__device__ float g_buf3[N_NODES * HDIM];

// ---------------- edge dtype probe -----------------------------------------
__global__ void detect_kernel(const void* __restrict__ ei) {
    const long long* p = (const long long*)ei;
    int mode = 1;
    for (int i = 0; i < 64; ++i) {
        long long v = p[i];
        if (v < 0 || v >= N_NODES) { mode = 0; break; }
    }
    g_mode = mode;
}

__device__ __forceinline__ int edge_at(const void* ei, long long idx) {
    if (g_mode) return (int)((const long long*)ei)[idx];
    return ((const int*)ei)[idx];
}

// ---------------- CSR build ------------------------------------------------
__global__ void zero2_kernel(int n) {
    int i = blockIdx.x * blockDim.x + threadIdx.x;
    if (i < n) { g_deg[i] = 0; g_cursor[i] = 0; }
}

__global__ void count_kernel(const void* __restrict__ ei, int E) {
    int e = blockIdx.x * blockDim.x + threadIdx.x;
    if (e < E) atomicAdd(&g_deg[edge_at(ei, (long long)E + e)], 1);
}

// 3-phase parallel exclusive scan over g_deg -> g_rowptr
__global__ void part_sum_kernel(int n) {
    __shared__ int s[256];
    int b = blockIdx.x, tid = threadIdx.x;
    int base = b * 1024;
    int v = 0;
    for (int i = tid; i < 1024; i += 256) {
        int idx = base + i;
        if (idx < n) v += g_deg[idx];
    }
    s[tid] = v; __syncthreads();
    for (int o = 128; o; o >>= 1) { if (tid < o) s[tid] += s[tid + o]; __syncthreads(); }
    if (tid == 0) g_part[b] = s[0];
}

__global__ void part_scan_kernel(int nb) {
    if (threadIdx.x == 0) {
        int acc = 0;
        for (int b = 0; b < nb; ++b) { int t = g_part[b]; g_part[b] = acc; acc += t; }
    }
}

__global__ void local_scan_kernel(int n) {
    __shared__ int s[1024];
    int tid = threadIdx.x;
    int i = blockIdx.x * 1024 + tid;
    int v = (i < n) ? g_deg[i] : 0;
    s[tid] = v; __syncthreads();
    for (int off = 1; off < 1024; off <<= 1) {
        int t = (tid >= off) ? s[tid - off] : 0;
        __syncthreads();
        s[tid] += t;
        __syncthreads();
    }
    int off0 = g_part[blockIdx.x];
    if (i < n)      g_rowptr[i] = off0 + s[tid] - v;   // exclusive
    if (i == n - 1) g_rowptr[n] = off0 + s[tid];       // total
}

__global__ void scatter_kernel(const void* __restrict__ ei, int E) {
    int e = blockIdx.x * blockDim.x + threadIdx.x;
    if (e < E) {
        int dst = edge_at(ei, (long long)E + e);
        int src = edge_at(ei, e);
        int pos = g_rowptr[dst] + atomicAdd(&g_cursor[dst], 1);
        g_srcs[pos] = src;
    }
}

// ---------------- segment max (one block per node, thread = feature) -------
template <int F>
__global__ void segmax_kernel(const float* __restrict__ in, float* __restrict__ out) {
    int n = blockIdx.x;
    int f = threadIdx.x;
    int beg = g_rowptr[n], end = g_rowptr[n + 1];
    float m = -FLT_MAX;
    int e = beg;
    for (; e + 8 <= end; e += 8) {
        float v0 = __ldg(&in[g_srcs[e    ] * F + f]);
        float v1 = __ldg(&in[g_srcs[e + 1] * F + f]);
        float v2 = __ldg(&in[g_srcs[e + 2] * F + f]);
        float v3 = __ldg(&in[g_srcs[e + 3] * F + f]);
        float v4 = __ldg(&in[g_srcs[e + 4] * F + f]);
        float v5 = __ldg(&in[g_srcs[e + 5] * F + f]);
        float v6 = __ldg(&in[g_srcs[e + 6] * F + f]);
        float v7 = __ldg(&in[g_srcs[e + 7] * F + f]);
        float a = fmaxf(fmaxf(v0, v1), fmaxf(v2, v3));
        float b = fmaxf(fmaxf(v4, v5), fmaxf(v6, v7));
        m = fmaxf(m, fmaxf(a, b));
    }
    for (; e < end; ++e) m = fmaxf(m, __ldg(&in[g_srcs[e] * F + f]));
    out[n * F + f] = (beg == end) ? 0.0f : m;
}

// ---------------- TF32 tensor-core dual-GEMM + bias + relu -----------------
// Cz[M,256] = relu(A0[M,K]@W0z[K,256] + A1[M,K]@W1z[K,256] + biasz)
// blockIdx.z selects {W0,W1,bias,C} set (head fusion); pass identical sets for z=1.
// BM=128, BN=128, BK=32. 256 threads = 8 warps, warp tile 32m x 64n.
// Software pipelined: next tile's LDG issued before the MMA block.
#define GBM 128
#define GBN 128
#define GBK 32
#define AS_STRIDE 36    // [m][k] pad: frag-read banks 4r+c -> conflict-free
#define BS_STRIDE 136   // [k][n] pad: frag-read banks 8c+r -> conflict-free

__device__ __forceinline__ uint32_t f2tf32(float x) {
    uint32_t u; asm("cvt.rna.tf32.f32 %0, %1;" : "=r"(u) : "f"(x)); return u;
}

__device__ __forceinline__ void mma_tf32(float* c, const uint32_t* a, const uint32_t* b) {
    asm volatile(
        "mma.sync.aligned.m16n8k8.row.col.f32.tf32.tf32.f32 "
        "{%0,%1,%2,%3}, {%4,%5,%6,%7}, {%8,%9}, {%0,%1,%2,%3};\n"
        : "+f"(c[0]), "+f"(c[1]), "+f"(c[2]), "+f"(c[3])
        : "r"(a[0]), "r"(a[1]), "r"(a[2]), "r"(a[3]), "r"(b[0]), "r"(b[1]));
}

__global__ __launch_bounds__(256, 2) void gemm2_tf32(
    const float* __restrict__ A0, const float* __restrict__ A1,
    const float* __restrict__ W0a, const float* __restrict__ W1a,
    const float* __restrict__ biasa, float* __restrict__ Ca,
    const float* __restrict__ W0b, const float* __restrict__ W1b,
    const float* __restrict__ biasb, float* __restrict__ Cb,
    int M, int K)
{
    __shared__ uint32_t As[GBM * AS_STRIDE];
    __shared__ uint32_t Bs[GBK * BS_STRIDE];
    const int tid  = threadIdx.x;
    const int lane = tid & 31, warp = tid >> 5;
    const int m0 = blockIdx.x * GBM, h0 = blockIdx.y * GBN;
    const int wm = warp >> 1, wn = warp & 1;   // 4x2 warp grid

    const float* __restrict__ W0   = blockIdx.z ? W0b   : W0a;
    const float* __restrict__ W1   = blockIdx.z ? W1b   : W1a;
    const float* __restrict__ bias = blockIdx.z ? biasb : biasa;
    float*       __restrict__ C    = blockIdx.z ? Cb    : Ca;

    float acc[2][8][4];
#pragma unroll
    for (int i = 0; i < 2; ++i)
#pragma unroll
        for (int j = 0; j < 8; ++j)
#pragma unroll
            for (int q = 0; q < 4; ++q) acc[i][j][q] = 0.f;

    const int a_kw = 4 * (lane & 7);   // A writer k offset (quarter-warp = one row)
    const int r = lane >> 2, c = lane & 3;
    const int KT = K >> 5;             // k-tiles per phase (4 or 8)
    const int T  = KT * 2;             // total tiles across both phases

    // A-row addresses for the 4 staged rows of this thread (constant over tiles)
    int mr_[4], gm_[4];
#pragma unroll
    for (int it = 0; it < 4; ++it) {
        mr_[it] = warp * 16 + it * 4 + (lane >> 3);
        gm_[it] = m0 + mr_[it];
    }
    const int kr_base = warp * 4;      // B staged rows: kr_base..kr_base+3

    float4 av[4], bv[4];
    auto LD = [&](int t) {
        const float* __restrict__ A = (t < KT) ? A0 : A1;
        const float* __restrict__ W = (t < KT) ? W0 : W1;
        int k0 = (t >= KT ? t - KT : t) << 5;
#pragma unroll
        for (int it = 0; it < 4; ++it) {
            av[it] = make_float4(0.f, 0.f, 0.f, 0.f);
            if (gm_[it] < M) av[it] = *(const float4*)&A[(size_t)gm_[it] * K + k0 + a_kw];
        }
#pragma unroll
        for (int it = 0; it < 4; ++it)
            bv[it] = *(const float4*)&W[(size_t)(k0 + kr_base + it) * HDIM + h0 + 4 * lane];
    };

    LD(0);   // prologue

#pragma unroll 1
    for (int t = 0; t < T; ++t) {
        // stage current tile from registers
#pragma unroll
        for (int it = 0; it < 4; ++it) {
            uint32_t* p = &As[mr_[it] * AS_STRIDE + a_kw];
            p[0] = f2tf32(av[it].x); p[1] = f2tf32(av[it].y);
            p[2] = f2tf32(av[it].z); p[3] = f2tf32(av[it].w);
        }
#pragma unroll
        for (int it = 0; it < 4; ++it) {
            uint32_t* p = &Bs[(kr_base + it) * BS_STRIDE + 4 * lane];
            p[0] = f2tf32(bv[it].x); p[1] = f2tf32(bv[it].y);
            p[2] = f2tf32(bv[it].z); p[3] = f2tf32(bv[it].w);
        }
        __syncthreads();

        // issue next tile's global loads; latency overlaps the MMA block below
        if (t + 1 < T) LD(t + 1);

#pragma unroll
        for (int kt = 0; kt < 4; ++kt) {
            uint32_t af[2][4], bf[8][2];
#pragma unroll
            for (int i = 0; i < 2; ++i) {
                int mb = wm * 32 + i * 16;
                af[i][0] = As[(mb + r    ) * AS_STRIDE + kt * 8 + c    ];
                af[i][1] = As[(mb + r + 8) * AS_STRIDE + kt * 8 + c    ];
                af[i][2] = As[(mb + r    ) * AS_STRIDE + kt * 8 + c + 4];
                af[i][3] = As[(mb + r + 8) * AS_STRIDE + kt * 8 + c + 4];
            }
#pragma unroll
            for (int j = 0; j < 8; ++j) {
                int nb = wn * 64 + j * 8 + r;
                bf[j][0] = Bs[(kt * 8 + c    ) * BS_STRIDE + nb];
                bf[j][1] = Bs[(kt * 8 + c + 4) * BS_STRIDE + nb];
            }
#pragma unroll
            for (int i = 0; i < 2; ++i)
#pragma unroll
                for (int j = 0; j < 8; ++j)
                    mma_tf32(acc[i][j], af[i], bf[j]);
        }
        __syncthreads();
    }

    // epilogue: bias + relu
    int c2 = (lane & 3) * 2;
#pragma unroll
    for (int i = 0; i < 2; ++i) {
        int gmb = m0 + wm * 32 + i * 16;
#pragma unroll
        for (int j = 0; j < 8; ++j) {
            int h = h0 + wn * 64 + j * 8 + c2;
            float bv0 = bias[h], bv1 = bias[h + 1];
            int gma = gmb + r, gmc = gmb + r + 8;
            if (gma < M) {
                float2 o = make_float2(fmaxf(acc[i][j][0] + bv0, 0.f),
                                       fmaxf(acc[i][j][1] + bv1, 0.f));
                *(float2*)&C[(size_t)gma * HDIM + h] = o;
            }
            if (gmc < M) {
                float2 o = make_float2(fmaxf(acc[i][j][2] + bv0, 0.f),
                                       fmaxf(acc[i][j][3] + bv1, 0.f));
                *(float2*)&C[(size_t)gmc * HDIM + h] = o;
            }
        }
    }
}

// ---------------- fused heads: out[n]=dot(h_rt)+ba ; out[N+n]=dot(h_mv)+bm --
__global__ void head_dot2(const float* __restrict__ h_rt, const float* __restrict__ w_rt,
                          const float* __restrict__ b_rt,
                          const float* __restrict__ h_mv, const float* __restrict__ w_mv,
                          const float* __restrict__ b_mv,
                          float* __restrict__ out, int M) {
    int gw = (blockIdx.x * blockDim.x + threadIdx.x) >> 5;
    int lane = threadIdx.x & 31;
    if (gw >= 2 * M) return;
    int which = gw >= M;
    int n = which ? gw - M : gw;
    const float* row = (which ? h_mv : h_rt) + (size_t)n * HDIM;
    const float* w   = which ? w_mv : w_rt;
    float s = 0.0f;
#pragma unroll
    for (int i = 0; i < HDIM; i += 32) s += row[i + lane] * w[i + lane];
#pragma unroll
    for (int o = 16; o; o >>= 1) s += __shfl_xor_sync(0xFFFFFFFFu, s, o);
    if (lane == 0) out[which * M + n] = s + (which ? b_mv[0] : b_rt[0]);
}

// ---------------- launch ---------------------------------------------------
extern "C" void kernel_launch(void* const* d_in, const int* in_sizes, int n_in,
                              void* d_out, int out_size) {
    const float* x  = (const float*)d_in[0];
    const void*  ei = d_in[1];   // int32 or int64 — probed on device
    const float *Wl1 = (const float*)d_in[2],  *bl1 = (const float*)d_in[3],  *Wr1 = (const float*)d_in[4];
    const float *Wl2 = (const float*)d_in[5],  *bl2 = (const float*)d_in[6],  *Wr2 = (const float*)d_in[7];
    const float *Wla = (const float*)d_in[8],  *bla = (const float*)d_in[9],  *Wra = (const float*)d_in[10];
    const float *Wa  = (const float*)d_in[11], *ba  = (const float*)d_in[12];
    const float *Wlm = (const float*)d_in[13], *blm = (const float*)d_in[14], *Wrm = (const float*)d_in[15];
    const float *Wm  = (const float*)d_in[16], *bm  = (const float*)d_in[17];
    float* out = (float*)d_out;

    const int N = N_NODES;
    const int E = in_sizes[1] / 2;
    const int NB = (N + 1023) / 1024;

    float *agg, *b1, *b2, *b3;
    cudaGetSymbolAddress((void**)&agg, g_agg);
    cudaGetSymbolAddress((void**)&b1,  g_buf1);
    cudaGetSymbolAddress((void**)&b2,  g_buf2);
    cudaGetSymbolAddress((void**)&b3,  g_buf3);

    // dtype probe + CSR build (max aggregation is order-invariant -> deterministic)
    detect_kernel    <<<1, 1>>>(ei);
    zero2_kernel     <<<(N + 255) / 256, 256>>>(N);
    count_kernel     <<<(E + 255) / 256, 256>>>(ei, E);
    part_sum_kernel  <<<NB, 256>>>(N);
    part_scan_kernel <<<1, 32>>>(NB);
    local_scan_kernel<<<NB, 1024>>>(N);
    scatter_kernel   <<<(E + 255) / 256, 256>>>(ei, E);

    dim3 gg1((N + GBM - 1) / GBM, HDIM / GBN, 1);
    dim3 gg2((N + GBM - 1) / GBM, HDIM / GBN, 2);

    // layer 1: h1 = relu(agg(x)@Wl1 + x@Wr1 + bl1)
    segmax_kernel<128><<<N, 128>>>(x, agg);
    gemm2_tf32<<<gg1, 256>>>(agg, x, Wl1, Wr1, bl1, b1,
                                     Wl1, Wr1, bl1, b1, N, 128);

    // layer 2: h2 = relu(agg(h1)@Wl2 + h1@Wr2 + bl2)
    segmax_kernel<256><<<N, 256>>>(b1, agg);
    gemm2_tf32<<<gg1, 256>>>(agg, b1, Wl2, Wr2, bl2, b2,
                                      Wl2, Wr2, bl2, b2, N, 256);

    // shared aggregation for both heads: agg(h2)
    segmax_kernel<256><<<N, 256>>>(b2, agg);

    // both head hidden layers in one launch (z=0: rtang -> b1, z=1: movedis -> b3)
    gemm2_tf32<<<gg2, 256>>>(agg, b2, Wla, Wra, bla, b1,
                                      Wlm, Wrm, blm, b3, N, 256);

    // both output heads in one launch
    head_dot2<<<(2 * N * 32 + 255) / 256, 256>>>(b1, Wa, ba, b3, Wm, bm, out, N);
}

// round 14
// speedup vs baseline: 2.6408x; 1.2337x over previous
#include <cuda_runtime.h>
#include <cuda_fp16.h>
#include <float.h>
#include <stdint.h>

#define N_NODES 50000
#define E_EDGES 800000
#define HDIM    256

// ---------------- scratch (static device globals; no runtime allocation) ----
__device__ int   g_mode;              // 0 = edge_index is int32, 1 = int64
__device__ int   g_deg[N_NODES];
__device__ int   g_cursor[N_NODES];
__device__ int   g_rowptr[N_NODES + 1];
__device__ int   g_part[64];
__device__ int   g_srcs[E_EDGES];
__device__ float g_agg [N_NODES * HDIM];
__device__ float g_buf1[N_NODES * HDIM];
__device__ float g_buf2[N_NODES * HDIM];
__device__ float g_buf3[N_NODES * HDIM];

// ---------------- edge dtype probe -----------------------------------------
__global__ void detect_kernel(const void* __restrict__ ei) {
    const long long* p = (const long long*)ei;
    int mode = 1;
    for (int i = 0; i < 64; ++i) {
        long long v = p[i];
        if (v < 0 || v >= N_NODES) { mode = 0; break; }
    }
    g_mode = mode;
}

__device__ __forceinline__ int edge_at(const void* ei, long long idx) {
    if (g_mode) return (int)((const long long*)ei)[idx];
    return ((const int*)ei)[idx];
}

// ---------------- CSR build ------------------------------------------------
__global__ void zero2_kernel(int n) {
    int i = blockIdx.x * blockDim.x + threadIdx.x;
    if (i < n) { g_deg[i] = 0; g_cursor[i] = 0; }
}

__global__ void count_kernel(const void* __restrict__ ei, int E) {
    int e = blockIdx.x * blockDim.x + threadIdx.x;
    if (e < E) atomicAdd(&g_deg[edge_at(ei, (long long)E + e)], 1);
}

__global__ void part_sum_kernel(int n) {
    __shared__ int s[256];
    int b = blockIdx.x, tid = threadIdx.x;
    int base = b * 1024;
    int v = 0;
    for (int i = tid; i < 1024; i += 256) {
        int idx = base + i;
        if (idx < n) v += g_deg[idx];
    }
    s[tid] = v; __syncthreads();
    for (int o = 128; o; o >>= 1) { if (tid < o) s[tid] += s[tid + o]; __syncthreads(); }
    if (tid == 0) g_part[b] = s[0];
}

__global__ void part_scan_kernel(int nb) {
    if (threadIdx.x == 0) {
        int acc = 0;
        for (int b = 0; b < nb; ++b) { int t = g_part[b]; g_part[b] = acc; acc += t; }
    }
}

__global__ void local_scan_kernel(int n) {
    __shared__ int s[1024];
    int tid = threadIdx.x;
    int i = blockIdx.x * 1024 + tid;
    int v = (i < n) ? g_deg[i] : 0;
    s[tid] = v; __syncthreads();
    for (int off = 1; off < 1024; off <<= 1) {
        int t = (tid >= off) ? s[tid - off] : 0;
        __syncthreads();
        s[tid] += t;
        __syncthreads();
    }
    int off0 = g_part[blockIdx.x];
    if (i < n)      g_rowptr[i] = off0 + s[tid] - v;
    if (i == n - 1) g_rowptr[n] = off0 + s[tid];
}

__global__ void scatter_kernel(const void* __restrict__ ei, int E) {
    int e = blockIdx.x * blockDim.x + threadIdx.x;
    if (e < E) {
        int dst = edge_at(ei, (long long)E + e);
        int src = edge_at(ei, e);
        int pos = g_rowptr[dst] + atomicAdd(&g_cursor[dst], 1);
        g_srcs[pos] = src;
    }
}

// ---------------- segment max (one block per node, thread = feature) -------
template <int F>
__global__ void segmax_kernel(const float* __restrict__ in, float* __restrict__ out) {
    int n = blockIdx.x;
    int f = threadIdx.x;
    int beg = g_rowptr[n], end = g_rowptr[n + 1];
    float m = -FLT_MAX;
    int e = beg;
    for (; e + 8 <= end; e += 8) {
        float v0 = __ldg(&in[g_srcs[e    ] * F + f]);
        float v1 = __ldg(&in[g_srcs[e + 1] * F + f]);
        float v2 = __ldg(&in[g_srcs[e + 2] * F + f]);
        float v3 = __ldg(&in[g_srcs[e + 3] * F + f]);
        float v4 = __ldg(&in[g_srcs[e + 4] * F + f]);
        float v5 = __ldg(&in[g_srcs[e + 5] * F + f]);
        float v6 = __ldg(&in[g_srcs[e + 6] * F + f]);
        float v7 = __ldg(&in[g_srcs[e + 7] * F + f]);
        float a = fmaxf(fmaxf(v0, v1), fmaxf(v2, v3));
        float b = fmaxf(fmaxf(v4, v5), fmaxf(v6, v7));
        m = fmaxf(m, fmaxf(a, b));
    }
    for (; e < end; ++e) m = fmaxf(m, __ldg(&in[g_srcs[e] * F + f]));
    out[n * F + f] = (beg == end) ? 0.0f : m;
}

// ---------------- FP16 tensor-core dual-GEMM + bias + relu -----------------
// Cz[M,256] = relu(A0[M,K]@W0z[K,256] + A1[M,K]@W1z[K,256] + biasz)
// fp16 inputs (same 10-bit mantissa as tf32), fp32 accumulation.
// BM=128, BN=128, BK=32. 256 threads = 8 warps (4x2), warp tile 32m x 64n,
// mma.sync.m16n8k16. A smem [m][kpair] stride 20 u32; B smem [kpair][n]
// stride 136 u32 — both conflict-free for fragment reads.
#define AS2 20
#define BS2 136

__device__ __forceinline__ uint32_t packh2(float lo, float hi) {
    __half2 h = __floats2half2_rn(lo, hi);   // lo -> low 16 bits
    return *(uint32_t*)&h;
}

__device__ __forceinline__ void mma_f16(float* c, const uint32_t* a, const uint32_t* b) {
    asm volatile(
        "mma.sync.aligned.m16n8k16.row.col.f32.f16.f16.f32 "
        "{%0,%1,%2,%3}, {%4,%5,%6,%7}, {%8,%9}, {%0,%1,%2,%3};\n"
        : "+f"(c[0]), "+f"(c[1]), "+f"(c[2]), "+f"(c[3])
        : "r"(a[0]), "r"(a[1]), "r"(a[2]), "r"(a[3]), "r"(b[0]), "r"(b[1]));
}

__global__ __launch_bounds__(256, 2) void gemm2_f16(
    const float* __restrict__ A0, const float* __restrict__ A1,
    const float* __restrict__ W0a, const float* __restrict__ W1a,
    const float* __restrict__ biasa, float* __restrict__ Ca,
    const float* __restrict__ W0b, const float* __restrict__ W1b,
    const float* __restrict__ biasb, float* __restrict__ Cb,
    int M, int K)
{
    __shared__ uint32_t As[128 * AS2];   // 128 m-rows x 16 k-pairs (+4 pad)
    __shared__ uint32_t Bs[16 * BS2];    // 16 k-pairs x 128 n (+8 pad)
    const int tid  = threadIdx.x;
    const int lane = tid & 31, warp = tid >> 5;
    const int m0 = blockIdx.x * 128, h0 = blockIdx.y * 128;
    const int wm = warp >> 1, wn = warp & 1;   // 4x2 warp grid

    const float* __restrict__ W0   = blockIdx.z ? W0b   : W0a;
    const float* __restrict__ W1   = blockIdx.z ? W1b   : W1a;
    const float* __restrict__ bias = blockIdx.z ? biasb : biasa;
    float*       __restrict__ C    = blockIdx.z ? Cb    : Ca;

    float acc[2][8][4];
#pragma unroll
    for (int i = 0; i < 2; ++i)
#pragma unroll
        for (int j = 0; j < 8; ++j)
#pragma unroll
            for (int q = 0; q < 4; ++q) acc[i][j][q] = 0.f;

    const int r = lane >> 2, c = lane & 3;
    const int KT = K >> 5;             // 32-K chunks per phase
    const int T  = KT * 2;

    // A staging geometry: thread covers 4 rows, 4 consecutive k at (lane&7)*4
    const int a_k4 = (lane & 7) * 4;
    int mr_[4], gm_[4];
#pragma unroll
    for (int it = 0; it < 4; ++it) {
        mr_[it] = warp * 16 + it * 4 + (lane >> 3);
        gm_[it] = m0 + mr_[it];
    }
    // B staging geometry: k-pair p, 8 consecutive n at n0
    const int b_p  = warp * 2 + (lane >> 4);   // 0..15
    const int b_n0 = (lane & 15) * 8;          // 0..120

    float4 av[4], bq0[2], bq1[2];
    auto LD = [&](int t) {
        const float* __restrict__ A = (t < KT) ? A0 : A1;
        const float* __restrict__ W = (t < KT) ? W0 : W1;
        int k0 = (t >= KT ? t - KT : t) << 5;
#pragma unroll
        for (int it = 0; it < 4; ++it) {
            av[it] = make_float4(0.f, 0.f, 0.f, 0.f);
            if (gm_[it] < M) av[it] = *(const float4*)&A[(size_t)gm_[it] * K + k0 + a_k4];
        }
        const float* w0 = &W[(size_t)(k0 + 2 * b_p    ) * HDIM + h0 + b_n0];
        const float* w1 = &W[(size_t)(k0 + 2 * b_p + 1) * HDIM + h0 + b_n0];
        bq0[0] = *(const float4*)(w0);     bq0[1] = *(const float4*)(w0 + 4);
        bq1[0] = *(const float4*)(w1);     bq1[1] = *(const float4*)(w1 + 4);
    };

    LD(0);   // prologue

#pragma unroll 1
    for (int t = 0; t < T; ++t) {
        // stage A: pack 4 floats -> 2 fp16x2, store uint2
#pragma unroll
        for (int it = 0; it < 4; ++it) {
            uint2 u;
            u.x = packh2(av[it].x, av[it].y);
            u.y = packh2(av[it].z, av[it].w);
            *(uint2*)&As[mr_[it] * AS2 + (a_k4 >> 1)] = u;
        }
        // stage B: pair k rows -> 8 fp16x2, two STS.128 (contiguous, conflict-free)
        {
            uint4 u0, u1;
            u0.x = packh2(bq0[0].x, bq1[0].x);
            u0.y = packh2(bq0[0].y, bq1[0].y);
            u0.z = packh2(bq0[0].z, bq1[0].z);
            u0.w = packh2(bq0[0].w, bq1[0].w);
            u1.x = packh2(bq0[1].x, bq1[1].x);
            u1.y = packh2(bq0[1].y, bq1[1].y);
            u1.z = packh2(bq0[1].z, bq1[1].z);
            u1.w = packh2(bq0[1].w, bq1[1].w);
            *(uint4*)&Bs[b_p * BS2 + b_n0]     = u0;
            *(uint4*)&Bs[b_p * BS2 + b_n0 + 4] = u1;
        }
        __syncthreads();

        // issue next chunk's global loads; latency overlaps the MMA block
        if (t + 1 < T) LD(t + 1);

#pragma unroll
        for (int kt = 0; kt < 2; ++kt) {     // two k16 steps cover 32 K
            uint32_t af[2][4], bf[8][2];
            int kp = kt * 8;
#pragma unroll
            for (int i = 0; i < 2; ++i) {
                int mb = wm * 32 + i * 16;
                af[i][0] = As[(mb + r    ) * AS2 + kp + c    ];
                af[i][1] = As[(mb + r + 8) * AS2 + kp + c    ];
                af[i][2] = As[(mb + r    ) * AS2 + kp + c + 4];
                af[i][3] = As[(mb + r + 8) * AS2 + kp + c + 4];
            }
#pragma unroll
            for (int j = 0; j < 8; ++j) {
                int nb = wn * 64 + j * 8 + r;
                bf[j][0] = Bs[(kp + c    ) * BS2 + nb];
                bf[j][1] = Bs[(kp + c + 4) * BS2 + nb];
            }
#pragma unroll
            for (int i = 0; i < 2; ++i)
#pragma unroll
                for (int j = 0; j < 8; ++j)
                    mma_f16(acc[i][j], af[i], bf[j]);
        }
        __syncthreads();
    }

    // epilogue: bias + relu (C frag layout same as tf32 m16n8k8: (r, 2c))
    int c2 = (lane & 3) * 2;
#pragma unroll
    for (int i = 0; i < 2; ++i) {
        int gmb = m0 + wm * 32 + i * 16;
#pragma unroll
        for (int j = 0; j < 8; ++j) {
            int h = h0 + wn * 64 + j * 8 + c2;
            float bv0 = bias[h], bv1 = bias[h + 1];
            int gma = gmb + r, gmc = gmb + r + 8;
            if (gma < M) {
                float2 o = make_float2(fmaxf(acc[i][j][0] + bv0, 0.f),
                                       fmaxf(acc[i][j][1] + bv1, 0.f));
                *(float2*)&C[(size_t)gma * HDIM + h] = o;
            }
            if (gmc < M) {
                float2 o = make_float2(fmaxf(acc[i][j][2] + bv0, 0.f),
                                       fmaxf(acc[i][j][3] + bv1, 0.f));
                *(float2*)&C[(size_t)gmc * HDIM + h] = o;
            }
        }
    }
}

// ---------------- fused heads ----------------------------------------------
__global__ void head_dot2(const float* __restrict__ h_rt, const float* __restrict__ w_rt,
                          const float* __restrict__ b_rt,
                          const float* __restrict__ h_mv, const float* __restrict__ w_mv,
                          const float* __restrict__ b_mv,
                          float* __restrict__ out, int M) {
    int gw = (blockIdx.x * blockDim.x + threadIdx.x) >> 5;
    int lane = threadIdx.x & 31;
    if (gw >= 2 * M) return;
    int which = gw >= M;
    int n = which ? gw - M : gw;
    const float* row = (which ? h_mv : h_rt) + (size_t)n * HDIM;
    const float* w   = which ? w_mv : w_rt;
    float s = 0.0f;
#pragma unroll
    for (int i = 0; i < HDIM; i += 32) s += row[i + lane] * w[i + lane];
#pragma unroll
    for (int o = 16; o; o >>= 1) s += __shfl_xor_sync(0xFFFFFFFFu, s, o);
    if (lane == 0) out[which * M + n] = s + (which ? b_mv[0] : b_rt[0]);
}

// ---------------- launch ---------------------------------------------------
extern "C" void kernel_launch(void* const* d_in, const int* in_sizes, int n_in,
                              void* d_out, int out_size) {
    const float* x  = (const float*)d_in[0];
    const void*  ei = d_in[1];   // int32 or int64 — probed on device
    const float *Wl1 = (const float*)d_in[2],  *bl1 = (const float*)d_in[3],  *Wr1 = (const float*)d_in[4];
    const float *Wl2 = (const float*)d_in[5],  *bl2 = (const float*)d_in[6],  *Wr2 = (const float*)d_in[7];
    const float *Wla = (const float*)d_in[8],  *bla = (const float*)d_in[9],  *Wra = (const float*)d_in[10];
    const float *Wa  = (const float*)d_in[11], *ba  = (const float*)d_in[12];
    const float *Wlm = (const float*)d_in[13], *blm = (const float*)d_in[14], *Wrm = (const float*)d_in[15];
    const float *Wm  = (const float*)d_in[16], *bm  = (const float*)d_in[17];
    float* out = (float*)d_out;

    const int N = N_NODES;
    const int E = in_sizes[1] / 2;
    const int NB = (N + 1023) / 1024;

    float *agg, *b1, *b2, *b3;
    cudaGetSymbolAddress((void**)&agg, g_agg);
    cudaGetSymbolAddress((void**)&b1,  g_buf1);
    cudaGetSymbolAddress((void**)&b2,  g_buf2);
    cudaGetSymbolAddress((void**)&b3,  g_buf3);

    // dtype probe + CSR build (max aggregation is order-invariant -> deterministic)
    detect_kernel    <<<1, 1>>>(ei);
    zero2_kernel     <<<(N + 255) / 256, 256>>>(N);
    count_kernel     <<<(E + 255) / 256, 256>>>(ei, E);
    part_sum_kernel  <<<NB, 256>>>(N);
    part_scan_kernel <<<1, 32>>>(NB);
    local_scan_kernel<<<NB, 1024>>>(N);
    scatter_kernel   <<<(E + 255) / 256, 256>>>(ei, E);

    dim3 gg1((N + 127) / 128, 2, 1);
    dim3 gg2((N + 127) / 128, 2, 2);

    // layer 1: h1 = relu(agg(x)@Wl1 + x@Wr1 + bl1)
    segmax_kernel<128><<<N, 128>>>(x, agg);
    gemm2_f16<<<gg1, 256>>>(agg, x, Wl1, Wr1, bl1, b1,
                                    Wl1, Wr1, bl1, b1, N, 128);

    // layer 2: h2 = relu(agg(h1)@Wl2 + h1@Wr2 + bl2)
    segmax_kernel<256><<<N, 256>>>(b1, agg);
    gemm2_f16<<<gg1, 256>>>(agg, b1, Wl2, Wr2, bl2, b2,
                                     Wl2, Wr2, bl2, b2, N, 256);

    // shared aggregation for both heads: agg(h2)
    segmax_kernel<256><<<N, 256>>>(b2, agg);

    // both head hidden layers in one launch (z=0: rtang -> b1, z=1: movedis -> b3)
    gemm2_f16<<<gg2, 256>>>(agg, b2, Wla, Wra, bla, b1,
                                     Wlm, Wrm, blm, b3, N, 256);

    // both output heads in one launch
    head_dot2<<<(2 * N * 32 + 255) / 256, 256>>>(b1, Wa, ba, b3, Wm, bm, out, N);
}

// round 17
// speedup vs baseline: 3.5602x; 1.3481x over previous
#include <cuda_runtime.h>
#include <cuda_fp16.h>
#include <float.h>
#include <stdint.h>

#define N_NODES 50000
#define E_EDGES 800000
#define HDIM    256

// ---------------- scratch (static device globals; no runtime allocation) ----
__device__ int      g_mode;
__device__ int      g_deg[N_NODES];
__device__ int      g_cursor[N_NODES];
__device__ int      g_rowptr[N_NODES + 1];
__device__ int      g_part[64];
__device__ int      g_srcs[E_EDGES];
// fp16 feature buffers (stored as u32 = half2 pairs)
__device__ uint32_t g_x16 [N_NODES * 64];    // x   [N,128] fp16
__device__ uint32_t g_agg16[N_NODES * 128];  // agg [N,256] fp16 (layer1 uses first 128 cols)
__device__ uint32_t g_h1  [N_NODES * 128];   // h1  [N,256] fp16
__device__ uint32_t g_h2  [N_NODES * 128];   // h2  [N,256] fp16
// fp32 head-hidden buffers
__device__ float    g_buf1[N_NODES * HDIM];
__device__ float    g_buf3[N_NODES * HDIM];
// prepacked fp16 weights: [K/2][256] u32, word = half2(W[2p][n], W[2p+1][n])
__device__ uint32_t g_wp[8][128 * 256];      // max K=256 -> 128 rows

// ---------------- edge dtype probe -----------------------------------------
__global__ void detect_kernel(const void* __restrict__ ei) {
    const long long* p = (const long long*)ei;
    int mode = 1;
    for (int i = 0; i < 64; ++i) {
        long long v = p[i];
        if (v < 0 || v >= N_NODES) { mode = 0; break; }
    }
    g_mode = mode;
}

__device__ __forceinline__ int edge_at(const void* ei, long long idx) {
    if (g_mode) return (int)((const long long*)ei)[idx];
    return ((const int*)ei)[idx];
}

// ---------------- CSR build ------------------------------------------------
__global__ void zero2_kernel(int n) {
    int i = blockIdx.x * blockDim.x + threadIdx.x;
    if (i < n) { g_deg[i] = 0; g_cursor[i] = 0; }
}

__global__ void count_kernel(const void* __restrict__ ei, int E) {
    int e = blockIdx.x * blockDim.x + threadIdx.x;
    if (e < E) atomicAdd(&g_deg[edge_at(ei, (long long)E + e)], 1);
}

__global__ void part_sum_kernel(int n) {
    __shared__ int s[256];
    int b = blockIdx.x, tid = threadIdx.x;
    int base = b * 1024;
    int v = 0;
    for (int i = tid; i < 1024; i += 256) {
        int idx = base + i;
        if (idx < n) v += g_deg[idx];
    }
    s[tid] = v; __syncthreads();
    for (int o = 128; o; o >>= 1) { if (tid < o) s[tid] += s[tid + o]; __syncthreads(); }
    if (tid == 0) g_part[b] = s[0];
}

__global__ void part_scan_kernel(int nb) {
    if (threadIdx.x == 0) {
        int acc = 0;
        for (int b = 0; b < nb; ++b) { int t = g_part[b]; g_part[b] = acc; acc += t; }
    }
}

__global__ void local_scan_kernel(int n) {
    __shared__ int s[1024];
    int tid = threadIdx.x;
    int i = blockIdx.x * 1024 + tid;
    int v = (i < n) ? g_deg[i] : 0;
    s[tid] = v; __syncthreads();
    for (int off = 1; off < 1024; off <<= 1) {
        int t = (tid >= off) ? s[tid - off] : 0;
        __syncthreads();
        s[tid] += t;
        __syncthreads();
    }
    int off0 = g_part[blockIdx.x];
    if (i < n)      g_rowptr[i] = off0 + s[tid] - v;
    if (i == n - 1) g_rowptr[n] = off0 + s[tid];
}

__global__ void scatter_kernel(const void* __restrict__ ei, int E) {
    int e = blockIdx.x * blockDim.x + threadIdx.x;
    if (e < E) {
        int dst = edge_at(ei, (long long)E + e);
        int src = edge_at(ei, e);
        int pos = g_rowptr[dst] + atomicAdd(&g_cursor[dst], 1);
        g_srcs[pos] = src;
    }
}

// ---------------- fp16 conversion / weight prepack -------------------------
__device__ __forceinline__ uint32_t packh2(float lo, float hi) {
    __half2 h = __floats2half2_rn(lo, hi);
    return *(uint32_t*)&h;
}

__global__ void convert_x_kernel(const float* __restrict__ x, uint32_t* __restrict__ x16, int n4) {
    int i = blockIdx.x * blockDim.x + threadIdx.x;
    if (i < n4) {
        float4 v = *(const float4*)&x[i * 4];
        x16[i * 2]     = packh2(v.x, v.y);
        x16[i * 2 + 1] = packh2(v.z, v.w);
    }
}

// P[p*256+n] = half2(W[2p][n], W[2p+1][n]) for W [K][256]
__global__ void pack_w_kernel(const float* __restrict__ W, uint32_t* __restrict__ P, int half_k) {
    int i = blockIdx.x * blockDim.x + threadIdx.x;
    if (i < half_k * 256) {
        int p = i >> 8, n = i & 255;
        P[i] = packh2(W[(2 * p) * 256 + n], W[(2 * p + 1) * 256 + n]);
    }
}

// ---------------- half2 segment max (block = node, thread = half2 column) --
template <int F2>
__global__ void segmax16_kernel(const uint32_t* __restrict__ in, uint32_t* __restrict__ out) {
    int n = blockIdx.x;
    int f = threadIdx.x;
    int beg = g_rowptr[n], end = g_rowptr[n + 1];
    const uint32_t NEGINF2 = 0xFC00FC00u;
    __half2 m = *(const __half2*)&NEGINF2;
    int e = beg;
    for (; e + 8 <= end; e += 8) {
        uint32_t u0 = __ldg(&in[g_srcs[e    ] * F2 + f]);
        uint32_t u1 = __ldg(&in[g_srcs[e + 1] * F2 + f]);
        uint32_t u2 = __ldg(&in[g_srcs[e + 2] * F2 + f]);
        uint32_t u3 = __ldg(&in[g_srcs[e + 3] * F2 + f]);
        uint32_t u4 = __ldg(&in[g_srcs[e + 4] * F2 + f]);
        uint32_t u5 = __ldg(&in[g_srcs[e + 5] * F2 + f]);
        uint32_t u6 = __ldg(&in[g_srcs[e + 6] * F2 + f]);
        uint32_t u7 = __ldg(&in[g_srcs[e + 7] * F2 + f]);
        __half2 a = __hmax2(__hmax2(*(__half2*)&u0, *(__half2*)&u1),
                            __hmax2(*(__half2*)&u2, *(__half2*)&u3));
        __half2 b = __hmax2(__hmax2(*(__half2*)&u4, *(__half2*)&u5),
                            __hmax2(*(__half2*)&u6, *(__half2*)&u7));
        m = __hmax2(m, __hmax2(a, b));
    }
    for (; e < end; ++e) {
        uint32_t u = __ldg(&in[g_srcs[e] * F2 + f]);
        m = __hmax2(m, *(__half2*)&u);
    }
    out[n * F2 + f] = (beg == end) ? 0u : *(uint32_t*)&m;
}

// ---------------- FP16 tensor-core dual-GEMM + bias + relu -----------------
// Cz[M,256] = relu(A0[M,K]@W0z + A1[M,K]@W1z + biasz); A fp16, W prepacked fp16,
// fp32 accumulate. HALF_OUT: store packed fp16 (u32) else fp32.
#define AS2 20
#define BS2 136

__device__ __forceinline__ void mma_f16(float* c, const uint32_t* a, const uint32_t* b) {
    asm volatile(
        "mma.sync.aligned.m16n8k16.row.col.f32.f16.f16.f32 "
        "{%0,%1,%2,%3}, {%4,%5,%6,%7}, {%8,%9}, {%0,%1,%2,%3};\n"
        : "+f"(c[0]), "+f"(c[1]), "+f"(c[2]), "+f"(c[3])
        : "r"(a[0]), "r"(a[1]), "r"(a[2]), "r"(a[3]), "r"(b[0]), "r"(b[1]));
}

template <bool HALF_OUT>
__global__ __launch_bounds__(256, 2) void gemm2_f16(
    const __half* __restrict__ A0, const __half* __restrict__ A1,
    const uint32_t* __restrict__ P0a, const uint32_t* __restrict__ P1a,
    const float* __restrict__ biasa, void* __restrict__ Ca,
    const uint32_t* __restrict__ P0b, const uint32_t* __restrict__ P1b,
    const float* __restrict__ biasb, void* __restrict__ Cb,
    int M, int K)
{
    __shared__ uint32_t As[128 * AS2];
    __shared__ uint32_t Bs[16 * BS2];
    const int tid  = threadIdx.x;
    const int lane = tid & 31, warp = tid >> 5;
    const int m0 = blockIdx.x * 128, h0 = blockIdx.y * 128;
    const int wm = warp >> 1, wn = warp & 1;

    const uint32_t* __restrict__ P0 = blockIdx.z ? P0b : P0a;
    const uint32_t* __restrict__ P1 = blockIdx.z ? P1b : P1a;
    const float* __restrict__ bias  = blockIdx.z ? biasb : biasa;
    void*        __restrict__ C     = blockIdx.z ? Cb : Ca;

    float acc[2][8][4];
#pragma unroll
    for (int i = 0; i < 2; ++i)
#pragma unroll
        for (int j = 0; j < 8; ++j)
#pragma unroll
            for (int q = 0; q < 4; ++q) acc[i][j][q] = 0.f;

    const int r = lane >> 2, c = lane & 3;
    const int KT = K >> 5;
    const int T  = KT * 2;

    const int a_k4 = (lane & 7) * 4;           // 4 consecutive k (2 kpairs)
    int mr_[4], gm_[4];
#pragma unroll
    for (int it = 0; it < 4; ++it) {
        mr_[it] = warp * 16 + it * 4 + (lane >> 3);
        gm_[it] = m0 + mr_[it];
    }
    const int b_p  = warp * 2 + (lane >> 4);   // kpair row 0..15
    const int b_n0 = (lane & 15) * 8;          // 8 n-values

    uint2 av[4];
    uint4 bq[2];
    auto LD = [&](int t) {
        const __half*   __restrict__ A = (t < KT) ? A0 : A1;
        const uint32_t* __restrict__ P = (t < KT) ? P0 : P1;
        int k0 = (t >= KT ? t - KT : t) << 5;
#pragma unroll
        for (int it = 0; it < 4; ++it) {
            av[it] = make_uint2(0u, 0u);
            if (gm_[it] < M) av[it] = *(const uint2*)&A[(size_t)gm_[it] * K + k0 + a_k4];
        }
        const uint32_t* pp = &P[(size_t)((k0 >> 1) + b_p) * 256 + h0 + b_n0];
        bq[0] = *(const uint4*)pp;
        bq[1] = *(const uint4*)(pp + 4);
    };

    LD(0);

#pragma unroll 1
    for (int t = 0; t < T; ++t) {
        // stage A (already fp16 kpairs)
#pragma unroll
        for (int it = 0; it < 4; ++it)
            *(uint2*)&As[mr_[it] * AS2 + (a_k4 >> 1)] = av[it];
        // stage B (prepacked, straight copy)
        *(uint4*)&Bs[b_p * BS2 + b_n0]     = bq[0];
        *(uint4*)&Bs[b_p * BS2 + b_n0 + 4] = bq[1];
        __syncthreads();

        if (t + 1 < T) LD(t + 1);

#pragma unroll
        for (int kt = 0; kt < 2; ++kt) {
            uint32_t af[2][4], bf[8][2];
            int kp = kt * 8;
#pragma unroll
            for (int i = 0; i < 2; ++i) {
                int mb = wm * 32 + i * 16;
                af[i][0] = As[(mb + r    ) * AS2 + kp + c    ];
                af[i][1] = As[(mb + r + 8) * AS2 + kp + c    ];
                af[i][2] = As[(mb + r    ) * AS2 + kp + c + 4];
                af[i][3] = As[(mb + r + 8) * AS2 + kp + c + 4];
            }
#pragma unroll
            for (int j = 0; j < 8; ++j) {
                int nb = wn * 64 + j * 8 + r;
                bf[j][0] = Bs[(kp + c    ) * BS2 + nb];
                bf[j][1] = Bs[(kp + c + 4) * BS2 + nb];
            }
#pragma unroll
            for (int i = 0; i < 2; ++i)
#pragma unroll
                for (int j = 0; j < 8; ++j)
                    mma_f16(acc[i][j], af[i], bf[j]);
        }
        __syncthreads();
    }

    // epilogue: bias + relu; fp16-packed or fp32 output
    int c2 = (lane & 3) * 2;
#pragma unroll
    for (int i = 0; i < 2; ++i) {
        int gmb = m0 + wm * 32 + i * 16;
#pragma unroll
        for (int j = 0; j < 8; ++j) {
            int h = h0 + wn * 64 + j * 8 + c2;
            float bv0 = bias[h], bv1 = bias[h + 1];
            int gma = gmb + r, gmc = gmb + r + 8;
            float o0 = fmaxf(acc[i][j][0] + bv0, 0.f);
            float o1 = fmaxf(acc[i][j][1] + bv1, 0.f);
            float o2 = fmaxf(acc[i][j][2] + bv0, 0.f);
            float o3 = fmaxf(acc[i][j][3] + bv1, 0.f);
            if (HALF_OUT) {
                uint32_t* C16 = (uint32_t*)C;
                if (gma < M) C16[(size_t)gma * 128 + (h >> 1)] = packh2(o0, o1);
                if (gmc < M) C16[(size_t)gmc * 128 + (h >> 1)] = packh2(o2, o3);
            } else {
                float* Cf = (float*)C;
                if (gma < M) *(float2*)&Cf[(size_t)gma * HDIM + h] = make_float2(o0, o1);
                if (gmc < M) *(float2*)&Cf[(size_t)gmc * HDIM + h] = make_float2(o2, o3);
            }
        }
    }
}

// ---------------- fused heads ----------------------------------------------
__global__ void head_dot2(const float* __restrict__ h_rt, const float* __restrict__ w_rt,
                          const float* __restrict__ b_rt,
                          const float* __restrict__ h_mv, const float* __restrict__ w_mv,
                          const float* __restrict__ b_mv,
                          float* __restrict__ out, int M) {
    int gw = (blockIdx.x * blockDim.x + threadIdx.x) >> 5;
    int lane = threadIdx.x & 31;
    if (gw >= 2 * M) return;
    int which = gw >= M;
    int n = which ? gw - M : gw;
    const float* row = (which ? h_mv : h_rt) + (size_t)n * HDIM;
    const float* w   = which ? w_mv : w_rt;
    float s = 0.0f;
#pragma unroll
    for (int i = 0; i < HDIM; i += 32) s += row[i + lane] * w[i + lane];
#pragma unroll
    for (int o = 16; o; o >>= 1) s += __shfl_xor_sync(0xFFFFFFFFu, s, o);
    if (lane == 0) out[which * M + n] = s + (which ? b_mv[0] : b_rt[0]);
}

// ---------------- launch ---------------------------------------------------
extern "C" void kernel_launch(void* const* d_in, const int* in_sizes, int n_in,
                              void* d_out, int out_size) {
    const float* x  = (const float*)d_in[0];
    const void*  ei = d_in[1];
    const float *Wl1 = (const float*)d_in[2],  *bl1 = (const float*)d_in[3],  *Wr1 = (const float*)d_in[4];
    const float *Wl2 = (const float*)d_in[5],  *bl2 = (const float*)d_in[6],  *Wr2 = (const float*)d_in[7];
    const float *Wla = (const float*)d_in[8],  *bla = (const float*)d_in[9],  *Wra = (const float*)d_in[10];
    const float *Wa  = (const float*)d_in[11], *ba  = (const float*)d_in[12];
    const float *Wlm = (const float*)d_in[13], *blm = (const float*)d_in[14], *Wrm = (const float*)d_in[15];
    const float *Wm  = (const float*)d_in[16], *bm  = (const float*)d_in[17];
    float* out = (float*)d_out;

    const int N = N_NODES;
    const int E = in_sizes[1] / 2;
    const int NB = (N + 1023) / 1024;

    uint32_t *x16, *agg16, *h1, *h2, *wp;
    float *b1, *b3;
    cudaGetSymbolAddress((void**)&x16,  g_x16);
    cudaGetSymbolAddress((void**)&agg16, g_agg16);
    cudaGetSymbolAddress((void**)&h1,   g_h1);
    cudaGetSymbolAddress((void**)&h2,   g_h2);
    cudaGetSymbolAddress((void**)&wp,   g_wp);
    cudaGetSymbolAddress((void**)&b1,   g_buf1);
    cudaGetSymbolAddress((void**)&b3,   g_buf3);
    uint32_t* WP[8];
    for (int i = 0; i < 8; ++i) WP[i] = wp + (size_t)i * 128 * 256;

    // CSR build + probes
    detect_kernel    <<<1, 1>>>(ei);
    zero2_kernel     <<<(N + 255) / 256, 256>>>(N);
    count_kernel     <<<(E + 255) / 256, 256>>>(ei, E);
    part_sum_kernel  <<<NB, 256>>>(N);
    part_scan_kernel <<<1, 32>>>(NB);
    local_scan_kernel<<<NB, 1024>>>(N);
    scatter_kernel   <<<(E + 255) / 256, 256>>>(ei, E);

    // fp16 conversions (overlap with CSR on same stream is serialized but cheap)
    convert_x_kernel<<<(N * 32 + 255) / 256, 256>>>(x, x16, N * 32);   // N*128/4 float4s
    pack_w_kernel<<<(64  * 256 + 255) / 256, 256>>>(Wl1, WP[0], 64);
    pack_w_kernel<<<(64  * 256 + 255) / 256, 256>>>(Wr1, WP[1], 64);
    pack_w_kernel<<<(128 * 256 + 255) / 256, 256>>>(Wl2, WP[2], 128);
    pack_w_kernel<<<(128 * 256 + 255) / 256, 256>>>(Wr2, WP[3], 128);
    pack_w_kernel<<<(128 * 256 + 255) / 256, 256>>>(Wla, WP[4], 128);
    pack_w_kernel<<<(128 * 256 + 255) / 256, 256>>>(Wra, WP[5], 128);
    pack_w_kernel<<<(128 * 256 + 255) / 256, 256>>>(Wlm, WP[6], 128);
    pack_w_kernel<<<(128 * 256 + 255) / 256, 256>>>(Wrm, WP[7], 128);

    dim3 gg1((N + 127) / 128, 2, 1);
    dim3 gg2((N + 127) / 128, 2, 2);

    // layer 1: h1 = relu(agg(x)@Wl1 + x@Wr1 + bl1)
    segmax16_kernel<64><<<N, 64>>>(x16, agg16);
    gemm2_f16<true><<<gg1, 256>>>((const __half*)agg16, (const __half*)x16,
                                  WP[0], WP[1], bl1, h1,
                                  WP[0], WP[1], bl1, h1, N, 128);
    // layer 2: h2 = relu(agg(h1)@Wl2 + h1@Wr2 + bl2)
    segmax16_kernel<128><<<N, 128>>>(h1, agg16);
    gemm2_f16<true><<<gg1, 256>>>((const __half*)agg16, (const __half*)h1,
                                  WP[2], WP[3], bl2, h2,
                                  WP[2], WP[3], bl2, h2, N, 256);
    // shared aggregation for both heads
    segmax16_kernel<128><<<N, 128>>>(h2, agg16);
    // both head hidden layers (z=0: rtang -> b1 fp32, z=1: movedis -> b3 fp32)
    gemm2_f16<false><<<gg2, 256>>>((const __half*)agg16, (const __half*)h2,
                                   WP[4], WP[5], bla, b1,
                                   WP[6], WP[7], blm, b3, N, 256);
    // both output heads
    head_dot2<<<(2 * N * 32 + 255) / 256, 256>>>(b1, Wa, ba, b3, Wm, bm, out, N);
}